// round 9
// baseline (speedup 1.0000x reference)
#include <cuda_runtime.h>
#include <cuda_fp16.h>
#include <math.h>
#include <stdint.h>

// ---------------------------------------------------------------------------
// DeepseekV2 MLA forward, B=1 S=2048 HID=2048 H=16 NOPE=128 ROPE=64 VD=128.
// Round 9: softmax fused away. QK epilogue emits per-block row stats (masked
// max + sum-of-exp) and its skipped blocks write the attn zero region; a tiny
// combine kernel produces per-row (M, 1/S); the PV gemm normalizes raw scores
// in-register (exp+mask) while writing the fp32 attn output and feeding fp16
// tiles to mma. fp16 attn copy and standalone softmax kernel deleted.
// ---------------------------------------------------------------------------

#define S_LEN 2048
#define HID   2048
#define HEADS 16
#define NOPE  128
#define ROPE  64
#define VD    128
#define QD    192
#define QLR   1536
#define KVLR  512
#define KVD_W (KVLR + 64)            // 576
#define QUP_N (HEADS * QD)           // 3072
#define KUP_N (HEADS * (NOPE + VD))  // 4096
#define WKD_PAD 640

// ---------------- fp32 scratch ----------------
#define F_QRAW 0L
#define F_QBUF (F_QRAW + (long)S_LEN * QLR)
#define F_KVD  (F_QBUF + (long)S_LEN * QUP_N)
#define F_KV   (F_KVD  + (long)S_LEN * KVD_W)
#define F_PST  (F_KV   + (long)S_LEN * KUP_N)            // pstats float2
#define F_RST  (F_PST  + (long)HEADS * 16 * S_LEN * 2)   // rowstats float2
#define F_TOT  (F_RST  + (long)HEADS * S_LEN * 2)

// ---------------- fp16 scratch ----------------
#define O_HID  0L
#define O_WQD  (O_HID  + (long)S_LEN * HID)
#define O_WQU  (O_WQD  + (long)QLR * HID)
#define O_WKD  (O_WQU  + (long)QUP_N * QLR)
#define O_WKU  (O_WKD  + (long)WKD_PAD * HID)
#define O_WO   (O_WKU  + (long)KUP_N * KVLR)
#define O_QRN  (O_WO   + (long)HID * (HEADS * VD))
#define O_KVN  (O_QRN  + (long)S_LEN * QLR)
#define O_QALL (O_KVN  + (long)S_LEN * KVLR)
#define O_KALL (O_QALL + (long)HEADS * S_LEN * QD)
#define O_KV16 (O_KALL + (long)HEADS * S_LEN * QD)
#define O_CTX  (O_KV16 + (long)S_LEN * KUP_N)
#define O_TOT  (O_CTX  + (long)S_LEN * HID)

__device__ __align__(256) float  g_f32[F_TOT];
__device__ __align__(256) __half g_h16[O_TOT];

// ---------------------------------------------------------------------------
__device__ __forceinline__ unsigned smem_u32(const void* p) {
    return (unsigned)__cvta_generic_to_shared(p);
}
__device__ __forceinline__ void ldm_x4(uint32_t r[4], unsigned addr) {
    asm volatile("ldmatrix.sync.aligned.m8n8.x4.shared.b16 {%0,%1,%2,%3}, [%4];"
                 : "=r"(r[0]), "=r"(r[1]), "=r"(r[2]), "=r"(r[3]) : "r"(addr));
}
__device__ __forceinline__ void ldm_x4t(uint32_t r[4], unsigned addr) {
    asm volatile("ldmatrix.sync.aligned.m8n8.x4.trans.shared.b16 {%0,%1,%2,%3}, [%4];"
                 : "=r"(r[0]), "=r"(r[1]), "=r"(r[2]), "=r"(r[3]) : "r"(addr));
}
__device__ __forceinline__ void mma16816(float d[4], const uint32_t a[4],
                                         const uint32_t b0, const uint32_t b1) {
    asm volatile(
        "mma.sync.aligned.m16n8k16.row.col.f32.f16.f16.f32 "
        "{%0,%1,%2,%3}, {%4,%5,%6,%7}, {%8,%9}, {%0,%1,%2,%3};"
        : "+f"(d[0]), "+f"(d[1]), "+f"(d[2]), "+f"(d[3])
        : "r"(a[0]), "r"(a[1]), "r"(a[2]), "r"(a[3]), "r"(b0), "r"(b1));
}
__device__ __forceinline__ void cp16(unsigned dst, const void* src) {
    asm volatile("cp.async.cg.shared.global [%0], [%1], 16;"
                 :: "r"(dst), "l"(src));
}
#define CP_COMMIT() asm volatile("cp.async.commit_group;" ::: "memory")
#define CP_WAIT1()  asm volatile("cp.async.wait_group 1;" ::: "memory")

// ---------------------------------------------------------------------------
__global__ void cvt_h(const float* __restrict__ x, __half* __restrict__ h,
                      long n)
{
    long i = ((long)blockIdx.x * 256 + threadIdx.x) * 4;
    if (i >= n) return;
    float4 v = *(const float4*)(x + i);
    __half2 a = __floats2half2_rn(v.x, v.y);
    __half2 b = __floats2half2_rn(v.z, v.w);
    uint2 u;
    u.x = *(uint32_t*)&a; u.y = *(uint32_t*)&b;
    *(uint2*)(h + i) = u;
}

// ---------------------------------------------------------------------------
// Tensor-core GEMM (mma.sync fp16), NT: C = scale*(A @ B^T)+bias.
// BM=128 BN=128 BK=32, 256 thr (8 warps 4m x 2n), 3-stage cp.async.
// CSKIP (QK): skipped blocks write zeros; computed blocks also emit per-row
// masked softmax partials (max, sum-exp) to pstats.
// ---------------------------------------------------------------------------
#define SST 40
#define STG 3
#define B_OFF 10240u
#define STAGE 20480u

template<bool CSKIP>
__global__ __launch_bounds__(256, 2)
void gemm_h(const __half* __restrict__ Ag, long sA,
            const __half* __restrict__ Bg, long sB,
            float* __restrict__ C, long sC,
            __half* __restrict__ Ch,
            int K, int lda, int ldb, int ldc, int Nvalid,
            const float* __restrict__ bias, float scale,
            float2* __restrict__ pstats)
{
    extern __shared__ __half sm[];

    const int bz = blockIdx.z;
    Ag += (long)bz * sA;
    Bg += (long)bz * sB;
    C  += (long)bz * sC;
    if (Ch) Ch += (long)bz * sC;

    const int row0 = blockIdx.y * 128;
    const int col0 = blockIdx.x * 128;
    const int tid = threadIdx.x;

    if (CSKIP && col0 >= row0 + 128) {
        // zero-fill this attn block (upper triangle)
        const int r = tid >> 1;
        float* dst = C + (long)(row0 + r) * ldc + col0 + (tid & 1) * 64;
        const float4 z = make_float4(0.f, 0.f, 0.f, 0.f);
#pragma unroll
        for (int i = 0; i < 16; i++) *(float4*)(dst + i * 4) = z;
        return;
    }

    const int nc = K >> 5;
    const int wid = tid >> 5, lane = tid & 31;
    const int wm = wid & 3, wn = wid >> 2;

    const int gr  = tid >> 1;
    const int gcb = (tid & 1) * 16;
    const __half* pA = Ag + (long)(row0 + gr) * lda + gcb;
    const __half* pB = Bg + (long)(col0 + gr) * ldb + gcb;
    const unsigned smb  = smem_u32(sm);
    const unsigned aoff = (unsigned)(gr * SST + gcb) * 2;
    const unsigned boff = B_OFF + aoff;

    float acc[2][8][4];
#pragma unroll
    for (int i = 0; i < 2; i++)
#pragma unroll
        for (int j = 0; j < 8; j++)
#pragma unroll
            for (int k = 0; k < 4; k++) acc[i][j][k] = 0.f;

    auto load_stage = [&](int kc, int slot) {
        const int k0 = kc << 5;
        const unsigned so = smb + (unsigned)slot * STAGE;
        cp16(so + aoff,      pA + k0);
        cp16(so + aoff + 16, pA + k0 + 8);
        cp16(so + boff,      pB + k0);
        cp16(so + boff + 16, pB + k0 + 8);
    };

#pragma unroll
    for (int s = 0; s < STG - 1; s++) {
        if (s < nc) load_stage(s, s);
        CP_COMMIT();
    }

    const int a_ri = lane & 15;
    const int a_k8 = (lane >> 4) << 3;
    const int b_ri = (lane & 7) + ((lane >> 4) << 3);
    const int b_k8 = ((lane >> 3) & 1) << 3;

    for (int c = 0; c < nc; ++c) {
        CP_WAIT1();
        __syncthreads();

        const unsigned so = smb + (unsigned)(c % STG) * STAGE;
#pragma unroll
        for (int kk = 0; kk < 2; kk++) {
            uint32_t af[2][4];
#pragma unroll
            for (int mi = 0; mi < 2; mi++) {
                unsigned ad = so +
                    (unsigned)((wm * 32 + mi * 16 + a_ri) * SST + kk * 16 + a_k8) * 2;
                ldm_x4(af[mi], ad);
            }
#pragma unroll
            for (int g = 0; g < 4; g++) {
                uint32_t bf[4];
                unsigned bd = so + B_OFF +
                    (unsigned)((wn * 64 + g * 16 + b_ri) * SST + kk * 16 + b_k8) * 2;
                ldm_x4(bf, bd);
#pragma unroll
                for (int mi = 0; mi < 2; mi++) {
                    mma16816(acc[mi][2*g],   af[mi], bf[0], bf[1]);
                    mma16816(acc[mi][2*g+1], af[mi], bf[2], bf[3]);
                }
            }
        }
        const int nx = c + STG - 1;
        if (nx < nc) load_stage(nx, nx % STG);
        CP_COMMIT();
    }

    // epilogue: store C (and optional fp16 copy)
#pragma unroll
    for (int mi = 0; mi < 2; mi++) {
        const int rb = row0 + wm * 32 + mi * 16 + (lane >> 2);
#pragma unroll
        for (int f = 0; f < 8; f++) {
            const int cc = col0 + wn * 64 + f * 8 + ((lane & 3) << 1);
            if (cc >= Nvalid) continue;
            float b0 = 0.f, b1 = 0.f;
            if (bias) { b0 = bias[cc]; b1 = bias[cc + 1]; }
            float2 v0, v1;
            v0.x = acc[mi][f][0] * scale + b0;
            v0.y = acc[mi][f][1] * scale + b1;
            v1.x = acc[mi][f][2] * scale + b0;
            v1.y = acc[mi][f][3] * scale + b1;
            *(float2*)&C[(long)rb * ldc + cc]       = v0;
            *(float2*)&C[(long)(rb + 8) * ldc + cc] = v1;
            if (Ch) {
                __half2 h0 = __floats2half2_rn(v0.x, v0.y);
                __half2 h1 = __floats2half2_rn(v1.x, v1.y);
                *(uint32_t*)&Ch[(long)rb * ldc + cc]       = *(uint32_t*)&h0;
                *(uint32_t*)&Ch[(long)(rb + 8) * ldc + cc] = *(uint32_t*)&h1;
            }
        }
    }

    // QK: per-row masked softmax partials for this 128-col block
    if (CSKIP && pstats) {
        __syncthreads();                     // reuse smem
        float2* sp = (float2*)sm;            // [2][128]
#pragma unroll
        for (int mi = 0; mi < 2; mi++) {
#pragma unroll
            for (int hf = 0; hf < 2; hf++) {
                const int ri = wm * 32 + mi * 16 + (lane >> 2) + hf * 8;
                const int rg = row0 + ri;
                float m = -INFINITY;
#pragma unroll
                for (int f = 0; f < 8; f++)
#pragma unroll
                    for (int j = 0; j < 2; j++) {
                        const int cc = col0 + wn * 64 + f * 8 + ((lane & 3) << 1) + j;
                        const float v = acc[mi][f][hf * 2 + j] * scale;
                        if (cc <= rg) m = fmaxf(m, v);
                    }
                m = fmaxf(m, __shfl_xor_sync(0xffffffffu, m, 1));
                m = fmaxf(m, __shfl_xor_sync(0xffffffffu, m, 2));
                float s = 0.f;
#pragma unroll
                for (int f = 0; f < 8; f++)
#pragma unroll
                    for (int j = 0; j < 2; j++) {
                        const int cc = col0 + wn * 64 + f * 8 + ((lane & 3) << 1) + j;
                        const float v = acc[mi][f][hf * 2 + j] * scale;
                        if (cc <= rg) s += expf(v - m);
                    }
                s += __shfl_xor_sync(0xffffffffu, s, 1);
                s += __shfl_xor_sync(0xffffffffu, s, 2);
                if ((lane & 3) == 0) sp[wn * 128 + ri] = make_float2(m, s);
            }
        }
        __syncthreads();
        if (tid < 128) {
            const float2 a = sp[tid];            // wn=0: always has valid col
            const float2 b = sp[128 + tid];
            const float M = fmaxf(a.x, b.x);
            const float S = a.y * expf(a.x - M) + b.y * expf(b.x - M);
            pstats[((long)bz * 16 + blockIdx.x) * S_LEN + row0 + tid] =
                make_float2(M, S);
        }
    }
}

// ---------------------------------------------------------------------------
// combine per-block partials -> per-row (M, 1/S). 1 warp per (head,row).
// ---------------------------------------------------------------------------
__global__ void combine_stats(const float2* __restrict__ ps,
                              float2* __restrict__ rs)
{
    const int g = blockIdx.x * 8 + (threadIdx.x >> 5);
    const int lane = threadIdx.x & 31;
    const int h = g >> 11, r = g & (S_LEN - 1);
    const int nx = (r >> 7) + 1;
    float m = -INFINITY, s = 0.f;
    if (lane < nx) {
        float2 p = ps[((long)h * 16 + lane) * S_LEN + r];
        m = p.x; s = p.y;
    }
    const float lm = m;
    for (int o = 16; o; o >>= 1) m = fmaxf(m, __shfl_xor_sync(0xffffffffu, m, o));
    float v = (lane < nx) ? s * expf(lm - m) : 0.f;
    for (int o = 16; o; o >>= 1) v += __shfl_xor_sync(0xffffffffu, v, o);
    if (lane == 0) rs[(long)h * S_LEN + r] = make_float2(m, 1.f / v);
}

// ---------------------------------------------------------------------------
// PV fused: per (head, 128-row block). Reads raw fp32 scores, normalizes
// (exp + causal mask) in registers, writes fp32 attn + fp16 smem tile, then
// mma with V (fp16 kv16, NN via ldmatrix.trans). Emits fp16 ctx.
// ---------------------------------------------------------------------------
#define BSTR 136
#define APITCH 10240u      // 128*SST*2
#define BBASE  20480u      // 2*APITCH
#define BPITCH 8704u       // 32*BSTR*2

__global__ __launch_bounds__(256, 2)
void pv_fused(float* __restrict__ attnF,
              const __half* __restrict__ kv16,
              const float2* __restrict__ rowstats,
              __half* __restrict__ ctxh)
{
    extern __shared__ __half sm[];
    const int h = blockIdx.z;
    const int row0 = blockIdx.y * 128;
    float* A = attnF + (long)h * S_LEN * S_LEN;
    const __half* B = kv16 + h * (NOPE + VD) + NOPE;
    const float2* rs = rowstats + (long)h * S_LEN;
    __half* ctxp = ctxh + h * VD;

    const int nc = (row0 + 128) >> 5;

    const int tid = threadIdx.x, wid = tid >> 5, lane = tid & 31;
    const int wm = wid & 3, wn = wid >> 2;

    // A transform geometry
    const int ar  = tid >> 1;
    const int acb = (tid & 1) * 16;
    const int Rg  = row0 + ar;
    const float2 st = rs[Rg];                 // (M, invS)
    float* gA = A + (long)Rg * S_LEN + acb;

    // B load geometry
    const int br = tid >> 3, bc = (tid & 7) * 16;
    const __half* pB = B + (long)br * KUP_N + bc;
    const unsigned smb = smem_u32(sm);
    const unsigned bso = (unsigned)(br * BSTR + bc) * 2;

    float acc[2][8][4];
#pragma unroll
    for (int i = 0; i < 2; i++)
#pragma unroll
        for (int j = 0; j < 8; j++)
#pragma unroll
            for (int k = 0; k < 4; k++) acc[i][j][k] = 0.f;

    float4 ra[4];
    auto loadA = [&](int kc) {
        const float* g = gA + (kc << 5);
        ra[0] = *(const float4*)g;
        ra[1] = *(const float4*)(g + 4);
        ra[2] = *(const float4*)(g + 8);
        ra[3] = *(const float4*)(g + 12);
    };
    auto loadB = [&](int kc, int slot) {
        const __half* b = pB + ((long)kc << 5) * KUP_N;
        const unsigned so = smb + BBASE + (unsigned)slot * BPITCH + bso;
        cp16(so, b);
        cp16(so + 16, b + 8);
    };
    auto xform = [&](int kc, int slot) {
        const int c0 = (kc << 5) + acb;
        float e[16];
        const float* rv = (const float*)ra;
#pragma unroll
        for (int q = 0; q < 16; q++) {
            const int cg = c0 + q;
            const float x = expf(rv[q] - st.x) * st.y;
            e[q] = (cg <= Rg) ? x : 0.f;
        }
        float* g = gA + (kc << 5);
        *(float4*)g        = make_float4(e[0],  e[1],  e[2],  e[3]);
        *(float4*)(g + 4)  = make_float4(e[4],  e[5],  e[6],  e[7]);
        *(float4*)(g + 8)  = make_float4(e[8],  e[9],  e[10], e[11]);
        *(float4*)(g + 12) = make_float4(e[12], e[13], e[14], e[15]);
        __half2 hh[8];
#pragma unroll
        for (int p = 0; p < 8; p++)
            hh[p] = __floats2half2_rn(e[2 * p], e[2 * p + 1]);
        __half* d = sm + slot * (APITCH / 2) + ar * SST + acb;
        *(uint4*)d       = *(uint4*)&hh[0];
        *(uint4*)(d + 8) = *(uint4*)&hh[4];
    };

    loadB(0, 0);
    CP_COMMIT();
    loadA(0);
    xform(0, 0);

    const int a_ri = lane & 15;
    const int a_k8 = (lane >> 4) << 3;
    const int t_kr = lane & 15;
    const int t_n8 = ((lane >> 4) & 1) << 3;

    for (int c = 0; c < nc; ++c) {
        if (c + 1 < nc) { loadA(c + 1); loadB(c + 1, (c + 1) & 1); }
        CP_COMMIT();
        CP_WAIT1();
        __syncthreads();

        const unsigned soA = smb + (unsigned)(c & 1) * APITCH;
        const unsigned soB = smb + BBASE + (unsigned)(c & 1) * BPITCH;
#pragma unroll
        for (int kk = 0; kk < 2; kk++) {
            uint32_t af[2][4];
#pragma unroll
            for (int mi = 0; mi < 2; mi++) {
                unsigned ad = soA +
                    (unsigned)((wm * 32 + mi * 16 + a_ri) * SST + kk * 16 + a_k8) * 2;
                ldm_x4(af[mi], ad);
            }
#pragma unroll
            for (int g = 0; g < 4; g++) {
                uint32_t bf[4];
                unsigned bd = soB +
                    (unsigned)((kk * 16 + t_kr) * BSTR + wn * 64 + g * 16 + t_n8) * 2;
                ldm_x4t(bf, bd);
#pragma unroll
                for (int mi = 0; mi < 2; mi++) {
                    mma16816(acc[mi][2*g],   af[mi], bf[0], bf[1]);
                    mma16816(acc[mi][2*g+1], af[mi], bf[2], bf[3]);
                }
            }
        }
        if (c + 1 < nc) xform(c + 1, (c + 1) & 1);
    }

    // epilogue: fp16 ctx only
#pragma unroll
    for (int mi = 0; mi < 2; mi++) {
        const int rb = row0 + wm * 32 + mi * 16 + (lane >> 2);
#pragma unroll
        for (int f = 0; f < 8; f++) {
            const int cc = wn * 64 + f * 8 + ((lane & 3) << 1);
            __half2 h0 = __floats2half2_rn(acc[mi][f][0], acc[mi][f][1]);
            __half2 h1 = __floats2half2_rn(acc[mi][f][2], acc[mi][f][3]);
            *(uint32_t*)&ctxp[(long)rb * HID + cc]       = *(uint32_t*)&h0;
            *(uint32_t*)&ctxp[(long)(rb + 8) * HID + cc] = *(uint32_t*)&h1;
        }
    }
}

// ---------------------------------------------------------------------------
__global__ void rmsnorm_h(const float* __restrict__ X,
                          const float* __restrict__ g,
                          __half* __restrict__ H, int n, int ldin)
{
    const float* x = X + (long)blockIdx.x * ldin;
    __half* h = H + (long)blockIdx.x * n;
    __shared__ float red[256];
    float s = 0.f;
    for (int i = threadIdx.x; i < n; i += 256) { float v = x[i]; s += v * v; }
    red[threadIdx.x] = s;
    __syncthreads();
    for (int o = 128; o > 0; o >>= 1) {
        if (threadIdx.x < o) red[threadIdx.x] += red[threadIdx.x + o];
        __syncthreads();
    }
    float r = rsqrtf(red[0] / (float)n + 1e-6f);
    for (int i = threadIdx.x; i < n; i += 256)
        h[i] = __float2half_rn(g[i] * x[i] * r);
}

// ---------------------------------------------------------------------------
__global__ void assemble_rope(const float* __restrict__ q,
                              const float* __restrict__ kvd,
                              const float* __restrict__ kv,
                              const int* __restrict__ pos_ids,
                              __half* __restrict__ qa,
                              __half* __restrict__ ka)
{
    const int s = blockIdx.x;
    const int t = threadIdx.x;
    __shared__ float cs[32], sn[32], kr[64];

    if (t < 32) {
        float pos = (float)pos_ids[s];
        double freq = exp(-log(10000.0) * (double)t / 32.0);
        float arg = pos * (float)freq;
        cs[t] = cosf(arg);
        sn[t] = sinf(arg);
    }
    __syncthreads();
    if (t < 32) {
        float x0 = kvd[(long)s * KVD_W + KVLR + 2 * t];
        float x1 = kvd[(long)s * KVD_W + KVLR + 2 * t + 1];
        kr[t]      = x0 * cs[t] - x1 * sn[t];
        kr[32 + t] = x1 * cs[t] + x0 * sn[t];
    }
    __syncthreads();

    for (int idx = t; idx < HEADS * QD; idx += 256) {
        int h = idx / QD, d = idx % QD;
        float qv, kvv;
        if (d < NOPE) {
            qv  = q[(long)s * QUP_N + h * QD + d];
            kvv = kv[(long)s * KUP_N + h * (NOPE + VD) + d];
        } else {
            int k = d - NOPE;
            int kk = k & 31;
            float x0 = q[(long)s * QUP_N + h * QD + NOPE + 2 * kk];
            float x1 = q[(long)s * QUP_N + h * QD + NOPE + 2 * kk + 1];
            qv = (k < 32) ? (x0 * cs[kk] - x1 * sn[kk])
                          : (x1 * cs[kk] + x0 * sn[kk]);
            kvv = kr[k];
        }
        long o = ((long)h * S_LEN + s) * QD + d;
        qa[o] = __float2half_rn(qv);
        ka[o] = __float2half_rn(kvv);
    }
}

// ---------------------------------------------------------------------------
extern "C" void kernel_launch(void* const* d_in, const int* in_sizes, int n_in,
                              void* d_out, int out_size)
{
    (void)in_sizes; (void)n_in; (void)out_size;
    const float* hid  = (const float*)d_in[0];
    const int*   pos  = (const int*)  d_in[1];
    const float* Wqd  = (const float*)d_in[3];
    const float* bqd  = (const float*)d_in[4];
    const float* gq   = (const float*)d_in[5];
    const float* Wqu  = (const float*)d_in[6];
    const float* Wkd  = (const float*)d_in[7];
    const float* bkd  = (const float*)d_in[8];
    const float* gkv  = (const float*)d_in[9];
    const float* Wku  = (const float*)d_in[10];
    const float* Wo   = (const float*)d_in[11];

    float* out  = (float*)d_out;
    float* attn = out + (long)S_LEN * HID;

    void *pf = nullptr, *ph = nullptr;
    cudaGetSymbolAddress(&pf, g_f32);
    cudaGetSymbolAddress(&ph, g_h16);
    float*  F = (float*)pf;
    __half* H = (__half*)ph;

    float* qraw = F + F_QRAW;
    float* qbuf = F + F_QBUF;
    float* kvd  = F + F_KVD;
    float* kv   = F + F_KV;
    float2* pst = (float2*)(F + F_PST);
    float2* rst = (float2*)(F + F_RST);

    const int SMEM_NT = STG * (int)STAGE;            // 61440
    const int SMEM_PV = 2 * (int)APITCH + 2 * (int)BPITCH;  // 37888
    static bool attr_done = false;
    if (!attr_done) {
        cudaFuncSetAttribute(gemm_h<false>,
            cudaFuncAttributeMaxDynamicSharedMemorySize, SMEM_NT);
        cudaFuncSetAttribute(gemm_h<true>,
            cudaFuncAttributeMaxDynamicSharedMemorySize, SMEM_NT);
        attr_done = true;
    }

    const dim3 blk(256);
    const float qk_scale = 0.07216878364870323f;   // 1/sqrt(192)

    // 0. convert inputs to fp16
    cvt_h<<<(unsigned)(((long)S_LEN*HID+1023)/1024), blk>>>(hid, H+O_HID, (long)S_LEN*HID);
    cvt_h<<<(unsigned)(((long)QLR*HID+1023)/1024), blk>>>(Wqd, H+O_WQD, (long)QLR*HID);
    cvt_h<<<(unsigned)(((long)QUP_N*QLR+1023)/1024), blk>>>(Wqu, H+O_WQU, (long)QUP_N*QLR);
    cvt_h<<<(unsigned)(((long)KVD_W*HID+1023)/1024), blk>>>(Wkd, H+O_WKD, (long)KVD_W*HID);
    cvt_h<<<(unsigned)(((long)KUP_N*KVLR+1023)/1024), blk>>>(Wku, H+O_WKU, (long)KUP_N*KVLR);
    cvt_h<<<(unsigned)(((long)HID*HEADS*VD+1023)/1024), blk>>>(Wo, H+O_WO, (long)HID*HEADS*VD);

    // 1. qraw = hid @ Wq_down^T + bq
    gemm_h<false><<<dim3(QLR/128, S_LEN/128, 1), blk, SMEM_NT>>>(
        H+O_HID, 0, H+O_WQD, 0, qraw, 0, nullptr,
        HID, HID, HID, QLR, QLR, bqd, 1.f, nullptr);
    // 2. rmsnorm -> fp16
    rmsnorm_h<<<S_LEN, blk>>>(qraw, gq, H+O_QRN, QLR, QLR);
    // 3. q = qrn @ Wq_up^T
    gemm_h<false><<<dim3(QUP_N/128, S_LEN/128, 1), blk, SMEM_NT>>>(
        H+O_QRN, 0, H+O_WQU, 0, qbuf, 0, nullptr,
        QLR, QLR, QLR, QUP_N, QUP_N, nullptr, 1.f, nullptr);
    // 4. kvd = hid @ Wkv_down^T + bkv
    gemm_h<false><<<dim3(WKD_PAD/128, S_LEN/128, 1), blk, SMEM_NT>>>(
        H+O_HID, 0, H+O_WKD, 0, kvd, 0, nullptr,
        HID, HID, HID, KVD_W, KVD_W, bkd, 1.f, nullptr);
    // 5. rmsnorm first 512 cols -> fp16
    rmsnorm_h<<<S_LEN, blk>>>(kvd, gkv, H+O_KVN, KVLR, KVD_W);
    // 6. kv = kvn @ Wkv_up^T ; epilogue emits fp16 kv16 copy
    gemm_h<false><<<dim3(KUP_N/128, S_LEN/128, 1), blk, SMEM_NT>>>(
        H+O_KVN, 0, H+O_WKU, 0, kv, 0, H+O_KV16,
        KVLR, KVLR, KVLR, KUP_N, KUP_N, nullptr, 1.f, nullptr);
    // 7. assemble + rope -> fp16 qall/kall
    assemble_rope<<<S_LEN, blk>>>(qbuf, kvd, kv, pos, H+O_QALL, H+O_KALL);
    // 8. QK: raw scores + zero blocks + per-block row stats
    gemm_h<true><<<dim3(S_LEN/128, S_LEN/128, HEADS), blk, SMEM_NT>>>(
        H+O_QALL, (long)S_LEN*QD, H+O_KALL, (long)S_LEN*QD,
        attn, (long)S_LEN*S_LEN, nullptr,
        QD, QD, QD, S_LEN, S_LEN, nullptr, qk_scale, pst);
    // 9. combine partials -> per-row (M, 1/S)
    combine_stats<<<HEADS * S_LEN / 8, blk>>>(pst, rst);
    // 10. PV fused: normalize + write attn fp32 + mma with V -> fp16 ctx
    pv_fused<<<dim3(1, S_LEN/128, HEADS), blk, SMEM_PV>>>(
        attn, H+O_KV16, rst, H+O_CTX);
    // 11. out = ctx @ Wo^T
    gemm_h<false><<<dim3(HID/128, S_LEN/128, 1), blk, SMEM_NT>>>(
        H+O_CTX, 0, H+O_WO, 0, out, 0, nullptr,
        HID, HID, HID, HID, HID, nullptr, 1.f, nullptr);
}